// round 16
// baseline (speedup 1.0000x reference)
#include <cuda_runtime.h>
#include <cuda_fp16.h>
#include <math.h>
#include <stdint.h>

#define N_NODESC 50000
#define N_PADROW 50048   // 391 * 128
#define NT_TILES 391
#define GRID_P   148
#define N_EDGESC 800000
#define CCH      128
#define N_GRAPHS 512
#define N_OUTC   5
#define BKT_CAP  96
#define PAD      136       // fp16 elems per SMEM row
#define TILE_B   34816     // 128*PAD*2 bytes

// ---------------- scratch (device globals: allocation-free) ----------------
__device__ __align__(128) __half g_hh[N_PADROW * CCH];   // A hi (fp16)
__device__ __align__(128) __half g_hl[N_PADROW * CCH];   // A lo (fp16)
__device__ __align__(128) float g_h1[N_PADROW * CCH];
__device__ __align__(128) float g_xo[N_NODESC * CCH];
__device__ __align__(128) float g_stats [2 * 2 * CCH];
__device__ __align__(128) float g_pool[N_GRAPHS * CCH];
__device__ __align__(128) int   g_deg[N_NODESC];
__device__ __align__(128) int2  g_bucket[N_NODESC * BKT_CAP];
__device__ __align__(128) __half g_w[4 * CCH * CCH];     // weights fp16

// ---------------- PTX helpers ------------------------------------------------
__device__ __forceinline__ uint32_t smem_u32(const void* p) {
    uint32_t a;
    asm("{ .reg .u64 t; cvta.to.shared.u64 t, %1; cvt.u32.u64 %0, t; }"
        : "=r"(a) : "l"(p));
    return a;
}
__device__ __forceinline__ void ldmx4(uint32_t* r, uint32_t a) {
    asm volatile("ldmatrix.sync.aligned.m8n8.x4.shared.b16 {%0,%1,%2,%3}, [%4];"
                 : "=r"(r[0]), "=r"(r[1]), "=r"(r[2]), "=r"(r[3]) : "r"(a));
}
__device__ __forceinline__ void ldmx2(uint32_t* r, uint32_t a) {
    asm volatile("ldmatrix.sync.aligned.m8n8.x2.shared.b16 {%0,%1}, [%2];"
                 : "=r"(r[0]), "=r"(r[1]) : "r"(a));
}
__device__ __forceinline__ void mma16816(float* d, const uint32_t* a, const uint32_t* b) {
    asm volatile("mma.sync.aligned.m16n8k16.row.col.f32.f16.f16.f32 "
                 "{%0,%1,%2,%3}, {%4,%5,%6,%7}, {%8,%9}, {%0,%1,%2,%3};"
                 : "+f"(d[0]), "+f"(d[1]), "+f"(d[2]), "+f"(d[3])
                 : "r"(a[0]), "r"(a[1]), "r"(a[2]), "r"(a[3]), "r"(b[0]), "r"(b[1]));
}
#define CP_A16(dst, src) \
    asm volatile("cp.async.cg.shared.global [%0], [%1], 16;" \
                 :: "r"(dst), "l"(src) : "memory")
#define CP_COMMIT() asm volatile("cp.async.commit_group;" ::: "memory")
#define CP_WAIT0()  asm volatile("cp.async.wait_group 0;" ::: "memory")

// fp16 hi/lo split: hi = rn(v), lo = rn(v - hi). 22-bit accurate pair.
__device__ __forceinline__ void hsplit2(float v0, float v1,
                                        uint32_t& hi, uint32_t& lo) {
    __half2 h = __floats2half2_rn(v0, v1);
    float r0 = v0 - __half2float(__low2half(h));
    float r1 = v1 - __half2float(__high2half(h));
    __half2 l = __floats2half2_rn(r0, r1);
    hi = *(uint32_t*)&h;
    lo = *(uint32_t*)&l;
}

// ---------------- fused setup ------------------------------------------------
__global__ void setup_kernel(const float* __restrict__ Wa,
                             const float* __restrict__ Wb,
                             const float* __restrict__ Wc,
                             const float* __restrict__ Wd) {
    int i = blockIdx.x * 256 + threadIdx.x;       // 0..65535
    if (i < N_GRAPHS * CCH) g_pool[i] = 0.f;
    if (i < N_NODESC) g_deg[i] = 0;
    if (i < 4 * CCH) g_stats[i] = 0.f;
    if (i < (N_PADROW - N_NODESC) * CCH) {        // zero pad rows
        size_t off = (size_t)N_NODESC * CCH + i;
        g_hh[off] = __float2half(0.f);
        g_hl[off] = __float2half(0.f);
        g_h1[off] = 0.f;
    }
    int w = i >> 14;
    int e = i & 16383;
    const float* src = (w == 0) ? Wa : (w == 1) ? Wb : (w == 2) ? Wc : Wd;
    g_w[i] = __float2half(src[e]);
}

// ---------------- bucket build ----------------------------------------------
__global__ void bucket_build_kernel(const int* __restrict__ ei,
                                    const float* __restrict__ ew) {
    int e = blockIdx.x * blockDim.x + threadIdx.x;
    if (e >= N_EDGESC) return;
    int s = ei[e];
    int d = ei[N_EDGESC + e];
    float w = ew[e];
    int p = atomicAdd(&g_deg[d], 1);
    g_bucket[(size_t)d * BKT_CAP + p] = make_int2(s, __float_as_int(w));
}

// ---------------- aggregation: 8 gathers in flight, fp16 hi/lo output -------
__global__ void __launch_bounds__(256)
node_agg_kernel(const float* __restrict__ x,
                const float* __restrict__ We,
                const float* __restrict__ be,
                __half* __restrict__ hh,
                __half* __restrict__ hl) {
    __shared__ float sWe[CCH];
    __shared__ float sbe[CCH];
    int t = threadIdx.x;
    if (t < CCH) sWe[t] = We[t];
    else         sbe[t - CCH] = be[t - CCH];
    __syncthreads();

    int warp = t >> 5;
    int lane = t & 31;
    int node = blockIdx.x * 8 + warp;
    if (node >= N_NODESC) return;

    int c = lane * 4;
    float w0 = sWe[c + 0], w1 = sWe[c + 1], w2 = sWe[c + 2], w3 = sWe[c + 3];
    float e0 = sbe[c + 0], e1 = sbe[c + 1], e2 = sbe[c + 2], e3 = sbe[c + 3];

    float4 acc = *(const float4*)(x + (size_t)node * CCH + c);
    float4 ac2 = make_float4(0.f, 0.f, 0.f, 0.f);

    int deg = __ldg(&g_deg[node]);
    const int2* bk = g_bucket + (size_t)node * BKT_CAP;

    int j = 0;
    // 8 independent gathers in flight per warp
    for (; j + 8 <= deg; j += 8) {
        int2 p[8];
#pragma unroll
        for (int q = 0; q < 8; q++) p[q] = __ldg(bk + j + q);
        float4 xv[8];
#pragma unroll
        for (int q = 0; q < 8; q++)
            xv[q] = *(const float4*)(x + (size_t)p[q].x * CCH + c);
#pragma unroll
        for (int q = 0; q < 8; q++) {
            float w = __int_as_float(p[q].y);
            float4* a = (q & 1) ? &ac2 : &acc;
            a->x += fmaxf(fmaf(w, w0, xv[q].x) + e0, 0.f);
            a->y += fmaxf(fmaf(w, w1, xv[q].y) + e1, 0.f);
            a->z += fmaxf(fmaf(w, w2, xv[q].z) + e2, 0.f);
            a->w += fmaxf(fmaf(w, w3, xv[q].w) + e3, 0.f);
        }
    }
    for (; j + 4 <= deg; j += 4) {
        int2 p[4];
#pragma unroll
        for (int q = 0; q < 4; q++) p[q] = __ldg(bk + j + q);
        float4 xv[4];
#pragma unroll
        for (int q = 0; q < 4; q++)
            xv[q] = *(const float4*)(x + (size_t)p[q].x * CCH + c);
#pragma unroll
        for (int q = 0; q < 4; q++) {
            float w = __int_as_float(p[q].y);
            float4* a = (q & 1) ? &ac2 : &acc;
            a->x += fmaxf(fmaf(w, w0, xv[q].x) + e0, 0.f);
            a->y += fmaxf(fmaf(w, w1, xv[q].y) + e1, 0.f);
            a->z += fmaxf(fmaf(w, w2, xv[q].z) + e2, 0.f);
            a->w += fmaxf(fmaf(w, w3, xv[q].w) + e3, 0.f);
        }
    }
    for (; j < deg; j++) {
        int2 p0 = __ldg(bk + j);
        float w = __int_as_float(p0.y);
        float4 xv = *(const float4*)(x + (size_t)p0.x * CCH + c);
        acc.x += fmaxf(fmaf(w, w0, xv.x) + e0, 0.f);
        acc.y += fmaxf(fmaf(w, w1, xv.y) + e1, 0.f);
        acc.z += fmaxf(fmaf(w, w2, xv.z) + e2, 0.f);
        acc.w += fmaxf(fmaf(w, w3, xv.w) + e3, 0.f);
    }
    acc.x += ac2.x; acc.y += ac2.y; acc.z += ac2.z; acc.w += ac2.w;

    uint2 hi, lo;
    hsplit2(acc.x, acc.y, hi.x, lo.x);
    hsplit2(acc.z, acc.w, hi.y, lo.y);
    *(uint2*)(hh + (size_t)node * CCH + c) = hi;
    *(uint2*)(hl + (size_t)node * CCH + c) = lo;
}

// ================= persistent GEMM1: h1 = h @ W1^T + b1, fused BN stats =====
// fp16 2-pass (AhB + AlB); B single fp16 fully hoisted to registers.
// 256 threads, 8 warps (2m x 4n), warp tile 64x32, static schedule, cp.async DB.
static constexpr int SMEM_G1 = TILE_B + 4 * TILE_B + (128 + 256) * 4; // 175616

__global__ void __launch_bounds__(256, 1)
gemm1_kernel(const __half* __restrict__ Ahg,
             const __half* __restrict__ Alg,
             const __half* __restrict__ W,
             const float* __restrict__ bias,
             float* __restrict__ stats_out,
             float* __restrict__ Cmat) {
    extern __shared__ char smraw[];
    char* pB  = smraw;
    char* pA  = smraw + TILE_B;
    float* sBias  = (float*)(smraw + 5 * TILE_B);
    float* sStats = sBias + 128;

    int tid  = threadIdx.x;
    int wid  = tid >> 5;
    int lane = tid & 31;
    int wm   = wid & 1;
    int wn   = wid >> 1;
    int bid  = blockIdx.x;

    uint32_t uB = smem_u32(pB);
    uint32_t uA = smem_u32(pA);

    if (tid < 128) sBias[tid] = bias[tid];

    // B tile once
#pragma unroll
    for (int i = 0; i < 8; i++) {
        int idx = tid + i * 256;
        int row = idx >> 4, c8 = idx & 15;
        uint32_t d = (uint32_t)((row * PAD + c8 * 8) * 2);
        CP_A16(uB + d, (const char*)W + idx * 16);
    }
    int t = bid;
    {
        size_t mb = (size_t)t * 128 * CCH * 2;
#pragma unroll
        for (int i = 0; i < 8; i++) {
            int idx = tid + i * 256;
            int row = idx >> 4, c8 = idx & 15;
            uint32_t d = (uint32_t)((row * PAD + c8 * 8) * 2);
            CP_A16(uA + d,          (const char*)Ahg + mb + idx * 16);
            CP_A16(uA + TILE_B + d, (const char*)Alg + mb + idx * 16);
        }
    }
    CP_COMMIT();
    CP_WAIT0();
    __syncthreads();

    int a_row = (lane & 7) + ((lane >> 3) & 1) * 8;
    int a_k   = (lane >> 4) * 8;
    int b_row = lane & 7;
    int b_k   = ((lane >> 3) & 1) * 8;

    // hoist ALL B fragments into registers (tile-invariant): 8ks x 4nt x 2
    uint32_t br[8][4][2];
#pragma unroll
    for (int ks = 0; ks < 8; ks++)
#pragma unroll
        for (int nt = 0; nt < 4; nt++) {
            uint32_t off = (uint32_t)(((wn * 32 + nt * 8 + b_row) * PAD + ks * 16 + b_k) * 2);
            ldmx2(br[ks][nt], uB + off);
        }

    float sums[4][2], sqs[4][2];
#pragma unroll
    for (int nt = 0; nt < 4; nt++) {
        sums[nt][0] = sums[nt][1] = 0.f;
        sqs[nt][0] = sqs[nt][1] = 0.f;
    }

    int cur = 0;
    while (true) {
        int nxt = t + GRID_P;
        if (nxt < NT_TILES) {
            uint32_t ub = uA + (cur ^ 1) * (2 * TILE_B);
            size_t mb = (size_t)nxt * 128 * CCH * 2;
#pragma unroll
            for (int i = 0; i < 8; i++) {
                int idx = tid + i * 256;
                int row = idx >> 4, c8 = idx & 15;
                uint32_t d = (uint32_t)((row * PAD + c8 * 8) * 2);
                CP_A16(ub + d,          (const char*)Ahg + mb + idx * 16);
                CP_A16(ub + TILE_B + d, (const char*)Alg + mb + idx * 16);
            }
            CP_COMMIT();
        }

        uint32_t uAh = uA + cur * (2 * TILE_B);
        uint32_t uAl = uAh + TILE_B;
        float acc[4][4][4];
#pragma unroll
        for (int i = 0; i < 4; i++)
#pragma unroll
            for (int j = 0; j < 4; j++)
#pragma unroll
                for (int q = 0; q < 4; q++) acc[i][j][q] = 0.f;

#pragma unroll
        for (int ks = 0; ks < 8; ks++) {
            int k0 = ks * 16;
            uint32_t ah[4][4], al[4][4];
#pragma unroll
            for (int mt = 0; mt < 4; mt++) {
                uint32_t off = (uint32_t)(((wm * 64 + mt * 16 + a_row) * PAD + k0 + a_k) * 2);
                ldmx4(ah[mt], uAh + off);
                ldmx4(al[mt], uAl + off);
            }
#pragma unroll
            for (int mt = 0; mt < 4; mt++)
#pragma unroll
                for (int nt = 0; nt < 4; nt++) {
                    mma16816(acc[mt][nt], ah[mt], br[ks][nt]);
                    mma16816(acc[mt][nt], al[mt], br[ks][nt]);
                }
        }

        int m0 = t * 128;
#pragma unroll
        for (int nt = 0; nt < 4; nt++) {
            int col = wn * 32 + nt * 8 + (lane & 3) * 2;
            float b0 = sBias[col], b1 = sBias[col + 1];
#pragma unroll
            for (int mt = 0; mt < 4; mt++) {
#pragma unroll
                for (int hf = 0; hf < 2; hf++) {
                    int m = m0 + wm * 64 + mt * 16 + (lane >> 2) + hf * 8;
                    if (m < N_NODESC) {
                        float v0 = acc[mt][nt][hf * 2 + 0] + b0;
                        float v1 = acc[mt][nt][hf * 2 + 1] + b1;
                        *(float2*)(Cmat + (size_t)m * CCH + col) = make_float2(v0, v1);
                        sums[nt][0] += v0; sums[nt][1] += v1;
                        sqs[nt][0] = fmaf(v0, v0, sqs[nt][0]);
                        sqs[nt][1] = fmaf(v1, v1, sqs[nt][1]);
                    }
                }
            }
        }

        if (nxt >= NT_TILES) break;
        CP_WAIT0();
        __syncthreads();
        cur ^= 1;
        t = nxt;
    }

    if (tid < 256) sStats[tid] = 0.f;
    __syncthreads();
#pragma unroll
    for (int nt = 0; nt < 4; nt++) {
        int col = wn * 32 + nt * 8 + (lane & 3) * 2;
        atomicAdd(&sStats[col],           sums[nt][0]);
        atomicAdd(&sStats[col + 1],       sums[nt][1]);
        atomicAdd(&sStats[128 + col],     sqs[nt][0]);
        atomicAdd(&sStats[128 + col + 1], sqs[nt][1]);
    }
    __syncthreads();
    if (tid < 256) atomicAdd(&stats_out[tid], sStats[tid]);
}

// ====== persistent GEMM2: out = relu( relu(BN(h1)) @ W2^T + b2 ) ============
static constexpr int SMEM_G2 = TILE_B + 2 * TILE_B + 65536 + 3 * 128 * 4; // 171520

template <bool POOL>
__global__ void __launch_bounds__(256, 1)
gemm2_kernel(const float* __restrict__ A,
             const __half* __restrict__ W,
             const float* __restrict__ bias,
             const float* __restrict__ stats_in,
             const float* __restrict__ gg,
             const float* __restrict__ bt,
             float* __restrict__ Cmat,
             const int* __restrict__ batch) {
    extern __shared__ char smraw[];
    char*  pB     = smraw;
    char*  pAh    = smraw + TILE_B;
    char*  pAl    = pAh + TILE_B;
    float* sStage = (float*)(smraw + 3 * TILE_B);
    float* sBias  = (float*)(smraw + 3 * TILE_B + 65536);
    float* sSc    = sBias + 128;
    float* sSh    = sSc + 128;

    int tid  = threadIdx.x;
    int wid  = tid >> 5;
    int lane = tid & 31;
    int wm   = wid & 1;
    int wn   = wid >> 1;
    int bid  = blockIdx.x;

    uint32_t uB  = smem_u32(pB);
    uint32_t uAh = smem_u32(pAh);
    uint32_t uAl = smem_u32(pAl);
    uint32_t uSt = smem_u32(sStage);

    if (tid < 128) {
        sBias[tid] = bias[tid];
        const float invN = 1.f / (float)N_NODESC;
        float mu  = stats_in[tid] * invN;
        float var = fmaf(-mu, mu, stats_in[CCH + tid] * invN);
        float rs  = rsqrtf(var + 1e-5f);
        float sc  = gg[tid] * rs;
        sSc[tid] = sc;
        sSh[tid] = fmaf(-mu, sc, bt[tid]);
    }

#pragma unroll
    for (int i = 0; i < 8; i++) {
        int idx = tid + i * 256;
        int row = idx >> 4, c8 = idx & 15;
        uint32_t d = (uint32_t)((row * PAD + c8 * 8) * 2);
        CP_A16(uB + d, (const char*)W + idx * 16);
    }
    int t = bid;
    {
        size_t mb = (size_t)t * 128 * CCH * 4;
#pragma unroll
        for (int i = 0; i < 16; i++) {
            int idx = tid + i * 256;
            CP_A16(uSt + idx * 16, (const char*)A + mb + idx * 16);
        }
    }
    CP_COMMIT();
    CP_WAIT0();
    __syncthreads();

    int a_row = (lane & 7) + ((lane >> 3) & 1) * 8;
    int a_k   = (lane >> 4) * 8;
    int b_row = lane & 7;
    int b_k   = ((lane >> 3) & 1) * 8;

    uint32_t br[8][4][2];
#pragma unroll
    for (int ks = 0; ks < 8; ks++)
#pragma unroll
        for (int nt = 0; nt < 4; nt++) {
            uint32_t off = (uint32_t)(((wn * 32 + nt * 8 + b_row) * PAD + ks * 16 + b_k) * 2);
            ldmx2(br[ks][nt], uB + off);
        }

    auto transform = [&]() {
        int r  = tid >> 1;
        int ch = (tid & 1) * 64;
        const float* srow = sStage + r * CCH + ch;
        uint32_t abase = (uint32_t)((r * PAD + ch) * 2);
#pragma unroll
        for (int q = 0; q < 64; q += 4) {
            float4 v = *(const float4*)(srow + q);
            int k = ch + q;
            v.x = fmaxf(fmaf(v.x, sSc[k + 0], sSh[k + 0]), 0.f);
            v.y = fmaxf(fmaf(v.y, sSc[k + 1], sSh[k + 1]), 0.f);
            v.z = fmaxf(fmaf(v.z, sSc[k + 2], sSh[k + 2]), 0.f);
            v.w = fmaxf(fmaf(v.w, sSc[k + 3], sSh[k + 3]), 0.f);
            uint2 hi, lo;
            hsplit2(v.x, v.y, hi.x, lo.x);
            hsplit2(v.z, v.w, hi.y, lo.y);
            *(uint2*)((char*)pAh + abase + q * 2) = hi;
            *(uint2*)((char*)pAl + abase + q * 2) = lo;
        }
    };
    transform();
    __syncthreads();

    while (true) {
        int nxt = t + GRID_P;
        if (nxt < NT_TILES) {
            size_t mb = (size_t)nxt * 128 * CCH * 4;
#pragma unroll
            for (int i = 0; i < 16; i++) {
                int idx = tid + i * 256;
                CP_A16(uSt + idx * 16, (const char*)A + mb + idx * 16);
            }
            CP_COMMIT();
        }

        float acc[4][4][4];
#pragma unroll
        for (int i = 0; i < 4; i++)
#pragma unroll
            for (int j = 0; j < 4; j++)
#pragma unroll
                for (int q = 0; q < 4; q++) acc[i][j][q] = 0.f;

#pragma unroll
        for (int ks = 0; ks < 8; ks++) {
            int k0 = ks * 16;
            uint32_t ah[4][4], al[4][4];
#pragma unroll
            for (int mt = 0; mt < 4; mt++) {
                uint32_t off = (uint32_t)(((wm * 64 + mt * 16 + a_row) * PAD + k0 + a_k) * 2);
                ldmx4(ah[mt], uAh + off);
                ldmx4(al[mt], uAl + off);
            }
#pragma unroll
            for (int mt = 0; mt < 4; mt++)
#pragma unroll
                for (int nt = 0; nt < 4; nt++) {
                    mma16816(acc[mt][nt], ah[mt], br[ks][nt]);
                    mma16816(acc[mt][nt], al[mt], br[ks][nt]);
                }
        }

        int m0 = t * 128;
#pragma unroll
        for (int nt = 0; nt < 4; nt++) {
            int col = wn * 32 + nt * 8 + (lane & 3) * 2;
            float b0 = sBias[col], b1 = sBias[col + 1];
#pragma unroll
            for (int mt = 0; mt < 4; mt++) {
#pragma unroll
                for (int hf = 0; hf < 2; hf++) {
                    int m = m0 + wm * 64 + mt * 16 + (lane >> 2) + hf * 8;
                    if (m < N_NODESC) {
                        float v0 = fmaxf(acc[mt][nt][hf * 2 + 0] + b0, 0.f);
                        float v1 = fmaxf(acc[mt][nt][hf * 2 + 1] + b1, 0.f);
                        if (POOL) {
                            int b = __ldg(batch + m);
                            int* prow = (int*)&g_pool[(size_t)b * CCH + col];
                            atomicMax(prow,     __float_as_int(v0));
                            atomicMax(prow + 1, __float_as_int(v1));
                        } else {
                            *(float2*)(Cmat + (size_t)m * CCH + col) = make_float2(v0, v1);
                        }
                    }
                }
            }
        }

        if (nxt >= NT_TILES) break;
        CP_WAIT0();
        __syncthreads();
        transform();
        __syncthreads();
        t = nxt;
    }
}

// ---------------- final linear ----------------------------------------------
__global__ void final_linear_kernel(const float* __restrict__ lw,
                                    const float* __restrict__ lb,
                                    float* __restrict__ out) {
    int gph  = blockIdx.x;
    int o    = threadIdx.x >> 5;
    int lane = threadIdx.x & 31;
    const float* p    = g_pool + (size_t)gph * CCH;
    const float* wrow = lw + (size_t)o * CCH;
    float s = 0.f;
    for (int c = lane; c < CCH; c += 32) s = fmaf(p[c], wrow[c], s);
#pragma unroll
    for (int d = 16; d; d >>= 1) s += __shfl_xor_sync(0xffffffffu, s, d);
    if (lane == 0) out[gph * N_OUTC + o] = s + lb[o];
}

// ---------------- launch -----------------------------------------------------
extern "C" void kernel_launch(void* const* d_in, const int* in_sizes, int n_in,
                              void* d_out, int out_size) {
    const float* x   = (const float*)d_in[0];
    const int*   ei  = (const int*)  d_in[1];
    const float* ew  = (const float*)d_in[2];
    const int*   bat = (const int*)  d_in[3];
    const float* P[18];
    for (int i = 0; i < 18; i++) P[i] = (const float*)d_in[4 + i];
    float* out = (float*)d_out;

    float *ph1, *pxo, *pst;
    __half *pw, *phh, *phl;
    cudaGetSymbolAddress((void**)&ph1, g_h1);
    cudaGetSymbolAddress((void**)&pxo, g_xo);
    cudaGetSymbolAddress((void**)&pst, g_stats);
    cudaGetSymbolAddress((void**)&pw,  g_w);
    cudaGetSymbolAddress((void**)&phh, g_hh);
    cudaGetSymbolAddress((void**)&phl, g_hl);

    cudaFuncSetAttribute(gemm1_kernel,
                         cudaFuncAttributeMaxDynamicSharedMemorySize, SMEM_G1);
    cudaFuncSetAttribute(gemm2_kernel<false>,
                         cudaFuncAttributeMaxDynamicSharedMemorySize, SMEM_G2);
    cudaFuncSetAttribute(gemm2_kernel<true>,
                         cudaFuncAttributeMaxDynamicSharedMemorySize, SMEM_G2);

    const int AGG_BLK = (N_NODESC + 7) / 8;

    setup_kernel<<<256, 256>>>(P[2], P[6], P[10], P[14]);
    bucket_build_kernel<<<(N_EDGESC + 255) / 256, 256>>>(ei, ew);

    const float* xin = x;
    for (int l = 0; l < 2; l++) {
        const float* We = P[l * 8 + 0];
        const float* be = P[l * 8 + 1];
        const float* b1 = P[l * 8 + 3];
        const float* gg = P[l * 8 + 4];
        const float* bt = P[l * 8 + 5];
        const float* b2 = P[l * 8 + 7];
        const __half* W1 = pw + (size_t)(l * 2 + 0) * CCH * CCH;
        const __half* W2 = pw + (size_t)(l * 2 + 1) * CCH * CCH;
        float* slot = pst + (size_t)l * 2 * CCH;

        node_agg_kernel<<<AGG_BLK, 256>>>(xin, We, be, phh, phl);
        gemm1_kernel<<<GRID_P, 256, SMEM_G1>>>(phh, phl, W1, b1, slot, ph1);
        if (l == 0) {
            gemm2_kernel<false><<<GRID_P, 256, SMEM_G2>>>(
                ph1, W2, b2, slot, gg, bt, pxo, bat);
        } else {
            gemm2_kernel<true><<<GRID_P, 256, SMEM_G2>>>(
                ph1, W2, b2, slot, gg, bt, pxo, bat);
        }
        xin = pxo;
    }

    final_linear_kernel<<<N_GRAPHS, 160>>>(P[16], P[17], out);
}

// round 17
// speedup vs baseline: 1.5240x; 1.5240x over previous
#include <cuda_runtime.h>
#include <cuda_fp16.h>
#include <math.h>
#include <stdint.h>

#define N_NODESC 50000
#define N_PADROW 50048   // 391 * 128
#define NT_TILES 391
#define GRID_P   148
#define N_EDGESC 800000
#define CCH      128
#define N_GRAPHS 512
#define N_OUTC   5
#define BKT_CAP  96
#define PAD      136       // fp16 elems per SMEM row
#define TILE_B   34816     // 128*PAD*2 bytes

// ---------------- scratch (device globals: allocation-free) ----------------
__device__ __align__(128) __half g_hh[N_PADROW * CCH];   // A hi (fp16)
__device__ __align__(128) __half g_hl[N_PADROW * CCH];   // A lo (fp16)
__device__ __align__(128) float g_h1[N_PADROW * CCH];
__device__ __align__(128) float g_xo[N_NODESC * CCH];
__device__ __align__(128) float g_stats [2 * 2 * CCH];
__device__ __align__(128) float g_pool[N_GRAPHS * CCH];
__device__ __align__(128) int   g_deg[N_NODESC];
__device__ __align__(128) int2  g_bucket[N_NODESC * BKT_CAP];
__device__ __align__(128) __half g_w[4 * CCH * CCH];     // weights fp16

// ---------------- PTX helpers ------------------------------------------------
__device__ __forceinline__ uint32_t smem_u32(const void* p) {
    uint32_t a;
    asm("{ .reg .u64 t; cvta.to.shared.u64 t, %1; cvt.u32.u64 %0, t; }"
        : "=r"(a) : "l"(p));
    return a;
}
__device__ __forceinline__ void ldmx4(uint32_t* r, uint32_t a) {
    asm volatile("ldmatrix.sync.aligned.m8n8.x4.shared.b16 {%0,%1,%2,%3}, [%4];"
                 : "=r"(r[0]), "=r"(r[1]), "=r"(r[2]), "=r"(r[3]) : "r"(a));
}
__device__ __forceinline__ void ldmx2(uint32_t* r, uint32_t a) {
    asm volatile("ldmatrix.sync.aligned.m8n8.x2.shared.b16 {%0,%1}, [%2];"
                 : "=r"(r[0]), "=r"(r[1]) : "r"(a));
}
__device__ __forceinline__ void mma16816(float* d, const uint32_t* a, const uint32_t* b) {
    asm volatile("mma.sync.aligned.m16n8k16.row.col.f32.f16.f16.f32 "
                 "{%0,%1,%2,%3}, {%4,%5,%6,%7}, {%8,%9}, {%0,%1,%2,%3};"
                 : "+f"(d[0]), "+f"(d[1]), "+f"(d[2]), "+f"(d[3])
                 : "r"(a[0]), "r"(a[1]), "r"(a[2]), "r"(a[3]), "r"(b[0]), "r"(b[1]));
}
#define CP_A16(dst, src) \
    asm volatile("cp.async.cg.shared.global [%0], [%1], 16;" \
                 :: "r"(dst), "l"(src) : "memory")
#define CP_COMMIT() asm volatile("cp.async.commit_group;" ::: "memory")
#define CP_WAIT0()  asm volatile("cp.async.wait_group 0;" ::: "memory")

// fp16 hi/lo split: hi = rn(v), lo = rn(v - hi). 22-bit accurate pair.
__device__ __forceinline__ void hsplit2(float v0, float v1,
                                        uint32_t& hi, uint32_t& lo) {
    __half2 h = __floats2half2_rn(v0, v1);
    float r0 = v0 - __half2float(__low2half(h));
    float r1 = v1 - __half2float(__high2half(h));
    __half2 l = __floats2half2_rn(r0, r1);
    hi = *(uint32_t*)&h;
    lo = *(uint32_t*)&l;
}

// ---------------- fused setup ------------------------------------------------
__global__ void setup_kernel(const float* __restrict__ Wa,
                             const float* __restrict__ Wb,
                             const float* __restrict__ Wc,
                             const float* __restrict__ Wd) {
    int i = blockIdx.x * 256 + threadIdx.x;       // 0..65535
    if (i < N_GRAPHS * CCH) g_pool[i] = 0.f;
    if (i < N_NODESC) g_deg[i] = 0;
    if (i < 4 * CCH) g_stats[i] = 0.f;
    if (i < (N_PADROW - N_NODESC) * CCH) {        // zero pad rows
        size_t off = (size_t)N_NODESC * CCH + i;
        g_hh[off] = __float2half(0.f);
        g_hl[off] = __float2half(0.f);
        g_h1[off] = 0.f;
    }
    int w = i >> 14;
    int e = i & 16383;
    const float* src = (w == 0) ? Wa : (w == 1) ? Wb : (w == 2) ? Wc : Wd;
    g_w[i] = __float2half(src[e]);
}

// ---------------- bucket build ----------------------------------------------
__global__ void bucket_build_kernel(const int* __restrict__ ei,
                                    const float* __restrict__ ew) {
    int e = blockIdx.x * blockDim.x + threadIdx.x;
    if (e >= N_EDGESC) return;
    int s = ei[e];
    int d = ei[N_EDGESC + e];
    float w = ew[e];
    int p = atomicAdd(&g_deg[d], 1);
    g_bucket[(size_t)d * BKT_CAP + p] = make_int2(s, __float_as_int(w));
}

// ---------------- aggregation (writes fp16 hi/lo split) ---------------------
__global__ void __launch_bounds__(256)
node_agg_kernel(const float* __restrict__ x,
                const float* __restrict__ We,
                const float* __restrict__ be,
                __half* __restrict__ hh,
                __half* __restrict__ hl) {
    __shared__ float sWe[CCH];
    __shared__ float sbe[CCH];
    int t = threadIdx.x;
    if (t < CCH) sWe[t] = We[t];
    else         sbe[t - CCH] = be[t - CCH];
    __syncthreads();

    int warp = t >> 5;
    int lane = t & 31;
    int node = blockIdx.x * 8 + warp;
    if (node >= N_NODESC) return;

    int c = lane * 4;
    float w0 = sWe[c + 0], w1 = sWe[c + 1], w2 = sWe[c + 2], w3 = sWe[c + 3];
    float e0 = sbe[c + 0], e1 = sbe[c + 1], e2 = sbe[c + 2], e3 = sbe[c + 3];

    float4 acc = *(const float4*)(x + (size_t)node * CCH + c);
    float4 ac2 = make_float4(0.f, 0.f, 0.f, 0.f);

    int deg = __ldg(&g_deg[node]);
    const int2* bk = g_bucket + (size_t)node * BKT_CAP;

    int j = 0;
    for (; j + 4 <= deg; j += 4) {
        int2 p0 = __ldg(bk + j);
        int2 p1 = __ldg(bk + j + 1);
        int2 p2 = __ldg(bk + j + 2);
        int2 p3 = __ldg(bk + j + 3);
        float wa = __int_as_float(p0.y);
        float wb = __int_as_float(p1.y);
        float wc = __int_as_float(p2.y);
        float wd = __int_as_float(p3.y);
        float4 xa = *(const float4*)(x + (size_t)p0.x * CCH + c);
        float4 xb = *(const float4*)(x + (size_t)p1.x * CCH + c);
        float4 xc = *(const float4*)(x + (size_t)p2.x * CCH + c);
        float4 xd = *(const float4*)(x + (size_t)p3.x * CCH + c);
        acc.x += fmaxf(fmaf(wa, w0, xa.x) + e0, 0.f);
        ac2.x += fmaxf(fmaf(wb, w0, xb.x) + e0, 0.f);
        acc.x += fmaxf(fmaf(wc, w0, xc.x) + e0, 0.f);
        ac2.x += fmaxf(fmaf(wd, w0, xd.x) + e0, 0.f);
        acc.y += fmaxf(fmaf(wa, w1, xa.y) + e1, 0.f);
        ac2.y += fmaxf(fmaf(wb, w1, xb.y) + e1, 0.f);
        acc.y += fmaxf(fmaf(wc, w1, xc.y) + e1, 0.f);
        ac2.y += fmaxf(fmaf(wd, w1, xd.y) + e1, 0.f);
        acc.z += fmaxf(fmaf(wa, w2, xa.z) + e2, 0.f);
        ac2.z += fmaxf(fmaf(wb, w2, xb.z) + e2, 0.f);
        acc.z += fmaxf(fmaf(wc, w2, xc.z) + e2, 0.f);
        ac2.z += fmaxf(fmaf(wd, w2, xd.z) + e2, 0.f);
        acc.w += fmaxf(fmaf(wa, w3, xa.w) + e3, 0.f);
        ac2.w += fmaxf(fmaf(wb, w3, xb.w) + e3, 0.f);
        acc.w += fmaxf(fmaf(wc, w3, xc.w) + e3, 0.f);
        ac2.w += fmaxf(fmaf(wd, w3, xd.w) + e3, 0.f);
    }
    for (; j < deg; j++) {
        int2 p0 = __ldg(bk + j);
        float wa = __int_as_float(p0.y);
        float4 xa = *(const float4*)(x + (size_t)p0.x * CCH + c);
        acc.x += fmaxf(fmaf(wa, w0, xa.x) + e0, 0.f);
        acc.y += fmaxf(fmaf(wa, w1, xa.y) + e1, 0.f);
        acc.z += fmaxf(fmaf(wa, w2, xa.z) + e2, 0.f);
        acc.w += fmaxf(fmaf(wa, w3, xa.w) + e3, 0.f);
    }
    acc.x += ac2.x; acc.y += ac2.y; acc.z += ac2.z; acc.w += ac2.w;

    uint2 hi, lo;
    hsplit2(acc.x, acc.y, hi.x, lo.x);
    hsplit2(acc.z, acc.w, hi.y, lo.y);
    *(uint2*)(hh + (size_t)node * CCH + c) = hi;
    *(uint2*)(hl + (size_t)node * CCH + c) = lo;
}

// ================= persistent GEMM1: h1 = h @ W1^T + b1, fused BN stats =====
// fp16 2-pass (AhB + AlB); B single fp16 fully hoisted to registers.
// 256 threads, 8 warps (2m x 4n), warp tile 64x32, static schedule, cp.async DB.
static constexpr int SMEM_G1 = TILE_B + 4 * TILE_B + (128 + 256) * 4; // 175616

__global__ void __launch_bounds__(256, 1)
gemm1_kernel(const __half* __restrict__ Ahg,
             const __half* __restrict__ Alg,
             const __half* __restrict__ W,
             const float* __restrict__ bias,
             float* __restrict__ stats_out,
             float* __restrict__ Cmat) {
    extern __shared__ char smraw[];
    char* pB  = smraw;
    char* pA  = smraw + TILE_B;
    float* sBias  = (float*)(smraw + 5 * TILE_B);
    float* sStats = sBias + 128;

    int tid  = threadIdx.x;
    int wid  = tid >> 5;
    int lane = tid & 31;
    int wm   = wid & 1;
    int wn   = wid >> 1;
    int bid  = blockIdx.x;

    uint32_t uB = smem_u32(pB);
    uint32_t uA = smem_u32(pA);

    if (tid < 128) sBias[tid] = bias[tid];

    // B tile once
#pragma unroll
    for (int i = 0; i < 8; i++) {
        int idx = tid + i * 256;
        int row = idx >> 4, c8 = idx & 15;
        uint32_t d = (uint32_t)((row * PAD + c8 * 8) * 2);
        CP_A16(uB + d, (const char*)W + idx * 16);
    }
    int t = bid;
    {
        size_t mb = (size_t)t * 128 * CCH * 2;
#pragma unroll
        for (int i = 0; i < 8; i++) {
            int idx = tid + i * 256;
            int row = idx >> 4, c8 = idx & 15;
            uint32_t d = (uint32_t)((row * PAD + c8 * 8) * 2);
            CP_A16(uA + d,          (const char*)Ahg + mb + idx * 16);
            CP_A16(uA + TILE_B + d, (const char*)Alg + mb + idx * 16);
        }
    }
    CP_COMMIT();
    CP_WAIT0();
    __syncthreads();

    int a_row = (lane & 7) + ((lane >> 3) & 1) * 8;
    int a_k   = (lane >> 4) * 8;
    int b_row = lane & 7;
    int b_k   = ((lane >> 3) & 1) * 8;

    // hoist ALL B fragments into registers (tile-invariant): 8ks x 4nt x 2
    uint32_t br[8][4][2];
#pragma unroll
    for (int ks = 0; ks < 8; ks++)
#pragma unroll
        for (int nt = 0; nt < 4; nt++) {
            uint32_t off = (uint32_t)(((wn * 32 + nt * 8 + b_row) * PAD + ks * 16 + b_k) * 2);
            ldmx2(br[ks][nt], uB + off);
        }

    float sums[4][2], sqs[4][2];
#pragma unroll
    for (int nt = 0; nt < 4; nt++) {
        sums[nt][0] = sums[nt][1] = 0.f;
        sqs[nt][0] = sqs[nt][1] = 0.f;
    }

    int cur = 0;
    while (true) {
        int nxt = t + GRID_P;
        if (nxt < NT_TILES) {
            uint32_t ub = uA + (cur ^ 1) * (2 * TILE_B);
            size_t mb = (size_t)nxt * 128 * CCH * 2;
#pragma unroll
            for (int i = 0; i < 8; i++) {
                int idx = tid + i * 256;
                int row = idx >> 4, c8 = idx & 15;
                uint32_t d = (uint32_t)((row * PAD + c8 * 8) * 2);
                CP_A16(ub + d,          (const char*)Ahg + mb + idx * 16);
                CP_A16(ub + TILE_B + d, (const char*)Alg + mb + idx * 16);
            }
            CP_COMMIT();
        }

        uint32_t uAh = uA + cur * (2 * TILE_B);
        uint32_t uAl = uAh + TILE_B;
        float acc[4][4][4];
#pragma unroll
        for (int i = 0; i < 4; i++)
#pragma unroll
            for (int j = 0; j < 4; j++)
#pragma unroll
                for (int q = 0; q < 4; q++) acc[i][j][q] = 0.f;

#pragma unroll
        for (int ks = 0; ks < 8; ks++) {
            int k0 = ks * 16;
            uint32_t ah[4][4], al[4][4];
#pragma unroll
            for (int mt = 0; mt < 4; mt++) {
                uint32_t off = (uint32_t)(((wm * 64 + mt * 16 + a_row) * PAD + k0 + a_k) * 2);
                ldmx4(ah[mt], uAh + off);
                ldmx4(al[mt], uAl + off);
            }
#pragma unroll
            for (int mt = 0; mt < 4; mt++)
#pragma unroll
                for (int nt = 0; nt < 4; nt++) {
                    mma16816(acc[mt][nt], ah[mt], br[ks][nt]);
                    mma16816(acc[mt][nt], al[mt], br[ks][nt]);
                }
        }

        int m0 = t * 128;
#pragma unroll
        for (int nt = 0; nt < 4; nt++) {
            int col = wn * 32 + nt * 8 + (lane & 3) * 2;
            float b0 = sBias[col], b1 = sBias[col + 1];
#pragma unroll
            for (int mt = 0; mt < 4; mt++) {
#pragma unroll
                for (int hf = 0; hf < 2; hf++) {
                    int m = m0 + wm * 64 + mt * 16 + (lane >> 2) + hf * 8;
                    if (m < N_NODESC) {
                        float v0 = acc[mt][nt][hf * 2 + 0] + b0;
                        float v1 = acc[mt][nt][hf * 2 + 1] + b1;
                        *(float2*)(Cmat + (size_t)m * CCH + col) = make_float2(v0, v1);
                        sums[nt][0] += v0; sums[nt][1] += v1;
                        sqs[nt][0] = fmaf(v0, v0, sqs[nt][0]);
                        sqs[nt][1] = fmaf(v1, v1, sqs[nt][1]);
                    }
                }
            }
        }

        if (nxt >= NT_TILES) break;
        CP_WAIT0();
        __syncthreads();
        cur ^= 1;
        t = nxt;
    }

    if (tid < 256) sStats[tid] = 0.f;
    __syncthreads();
#pragma unroll
    for (int nt = 0; nt < 4; nt++) {
        int col = wn * 32 + nt * 8 + (lane & 3) * 2;
        atomicAdd(&sStats[col],           sums[nt][0]);
        atomicAdd(&sStats[col + 1],       sums[nt][1]);
        atomicAdd(&sStats[128 + col],     sqs[nt][0]);
        atomicAdd(&sStats[128 + col + 1], sqs[nt][1]);
    }
    __syncthreads();
    if (tid < 256) atomicAdd(&stats_out[tid], sStats[tid]);
}

// ====== persistent GEMM2: out = relu( relu(BN(h1)) @ W2^T + b2 ) ============
static constexpr int SMEM_G2 = TILE_B + 2 * TILE_B + 65536 + 3 * 128 * 4; // 171520

template <bool POOL>
__global__ void __launch_bounds__(256, 1)
gemm2_kernel(const float* __restrict__ A,
             const __half* __restrict__ W,
             const float* __restrict__ bias,
             const float* __restrict__ stats_in,
             const float* __restrict__ gg,
             const float* __restrict__ bt,
             float* __restrict__ Cmat,
             const int* __restrict__ batch) {
    extern __shared__ char smraw[];
    char*  pB     = smraw;
    char*  pAh    = smraw + TILE_B;
    char*  pAl    = pAh + TILE_B;
    float* sStage = (float*)(smraw + 3 * TILE_B);
    float* sBias  = (float*)(smraw + 3 * TILE_B + 65536);
    float* sSc    = sBias + 128;
    float* sSh    = sSc + 128;

    int tid  = threadIdx.x;
    int wid  = tid >> 5;
    int lane = tid & 31;
    int wm   = wid & 1;
    int wn   = wid >> 1;
    int bid  = blockIdx.x;

    uint32_t uB  = smem_u32(pB);
    uint32_t uAh = smem_u32(pAh);
    uint32_t uAl = smem_u32(pAl);
    uint32_t uSt = smem_u32(sStage);

    if (tid < 128) {
        sBias[tid] = bias[tid];
        const float invN = 1.f / (float)N_NODESC;
        float mu  = stats_in[tid] * invN;
        float var = fmaf(-mu, mu, stats_in[CCH + tid] * invN);
        float rs  = rsqrtf(var + 1e-5f);
        float sc  = gg[tid] * rs;
        sSc[tid] = sc;
        sSh[tid] = fmaf(-mu, sc, bt[tid]);
    }

#pragma unroll
    for (int i = 0; i < 8; i++) {
        int idx = tid + i * 256;
        int row = idx >> 4, c8 = idx & 15;
        uint32_t d = (uint32_t)((row * PAD + c8 * 8) * 2);
        CP_A16(uB + d, (const char*)W + idx * 16);
    }
    int t = bid;
    {
        size_t mb = (size_t)t * 128 * CCH * 4;
#pragma unroll
        for (int i = 0; i < 16; i++) {
            int idx = tid + i * 256;
            CP_A16(uSt + idx * 16, (const char*)A + mb + idx * 16);
        }
    }
    CP_COMMIT();
    CP_WAIT0();
    __syncthreads();

    int a_row = (lane & 7) + ((lane >> 3) & 1) * 8;
    int a_k   = (lane >> 4) * 8;
    int b_row = lane & 7;
    int b_k   = ((lane >> 3) & 1) * 8;

    uint32_t br[8][4][2];
#pragma unroll
    for (int ks = 0; ks < 8; ks++)
#pragma unroll
        for (int nt = 0; nt < 4; nt++) {
            uint32_t off = (uint32_t)(((wn * 32 + nt * 8 + b_row) * PAD + ks * 16 + b_k) * 2);
            ldmx2(br[ks][nt], uB + off);
        }

    auto transform = [&]() {
        int r  = tid >> 1;
        int ch = (tid & 1) * 64;
        const float* srow = sStage + r * CCH + ch;
        uint32_t abase = (uint32_t)((r * PAD + ch) * 2);
#pragma unroll
        for (int q = 0; q < 64; q += 4) {
            float4 v = *(const float4*)(srow + q);
            int k = ch + q;
            v.x = fmaxf(fmaf(v.x, sSc[k + 0], sSh[k + 0]), 0.f);
            v.y = fmaxf(fmaf(v.y, sSc[k + 1], sSh[k + 1]), 0.f);
            v.z = fmaxf(fmaf(v.z, sSc[k + 2], sSh[k + 2]), 0.f);
            v.w = fmaxf(fmaf(v.w, sSc[k + 3], sSh[k + 3]), 0.f);
            uint2 hi, lo;
            hsplit2(v.x, v.y, hi.x, lo.x);
            hsplit2(v.z, v.w, hi.y, lo.y);
            *(uint2*)((char*)pAh + abase + q * 2) = hi;
            *(uint2*)((char*)pAl + abase + q * 2) = lo;
        }
    };
    transform();
    __syncthreads();

    while (true) {
        int nxt = t + GRID_P;
        if (nxt < NT_TILES) {
            size_t mb = (size_t)nxt * 128 * CCH * 4;
#pragma unroll
            for (int i = 0; i < 16; i++) {
                int idx = tid + i * 256;
                CP_A16(uSt + idx * 16, (const char*)A + mb + idx * 16);
            }
            CP_COMMIT();
        }

        float acc[4][4][4];
#pragma unroll
        for (int i = 0; i < 4; i++)
#pragma unroll
            for (int j = 0; j < 4; j++)
#pragma unroll
                for (int q = 0; q < 4; q++) acc[i][j][q] = 0.f;

#pragma unroll
        for (int ks = 0; ks < 8; ks++) {
            int k0 = ks * 16;
            uint32_t ah[4][4], al[4][4];
#pragma unroll
            for (int mt = 0; mt < 4; mt++) {
                uint32_t off = (uint32_t)(((wm * 64 + mt * 16 + a_row) * PAD + k0 + a_k) * 2);
                ldmx4(ah[mt], uAh + off);
                ldmx4(al[mt], uAl + off);
            }
#pragma unroll
            for (int mt = 0; mt < 4; mt++)
#pragma unroll
                for (int nt = 0; nt < 4; nt++) {
                    mma16816(acc[mt][nt], ah[mt], br[ks][nt]);
                    mma16816(acc[mt][nt], al[mt], br[ks][nt]);
                }
        }

        int m0 = t * 128;
#pragma unroll
        for (int nt = 0; nt < 4; nt++) {
            int col = wn * 32 + nt * 8 + (lane & 3) * 2;
            float b0 = sBias[col], b1 = sBias[col + 1];
#pragma unroll
            for (int mt = 0; mt < 4; mt++) {
#pragma unroll
                for (int hf = 0; hf < 2; hf++) {
                    int m = m0 + wm * 64 + mt * 16 + (lane >> 2) + hf * 8;
                    if (m < N_NODESC) {
                        float v0 = fmaxf(acc[mt][nt][hf * 2 + 0] + b0, 0.f);
                        float v1 = fmaxf(acc[mt][nt][hf * 2 + 1] + b1, 0.f);
                        if (POOL) {
                            int b = __ldg(batch + m);
                            int* prow = (int*)&g_pool[(size_t)b * CCH + col];
                            atomicMax(prow,     __float_as_int(v0));
                            atomicMax(prow + 1, __float_as_int(v1));
                        } else {
                            *(float2*)(Cmat + (size_t)m * CCH + col) = make_float2(v0, v1);
                        }
                    }
                }
            }
        }

        if (nxt >= NT_TILES) break;
        CP_WAIT0();
        __syncthreads();
        transform();
        __syncthreads();
        t = nxt;
    }
}

// ---------------- final linear ----------------------------------------------
__global__ void final_linear_kernel(const float* __restrict__ lw,
                                    const float* __restrict__ lb,
                                    float* __restrict__ out) {
    int gph  = blockIdx.x;
    int o    = threadIdx.x >> 5;
    int lane = threadIdx.x & 31;
    const float* p    = g_pool + (size_t)gph * CCH;
    const float* wrow = lw + (size_t)o * CCH;
    float s = 0.f;
    for (int c = lane; c < CCH; c += 32) s = fmaf(p[c], wrow[c], s);
#pragma unroll
    for (int d = 16; d; d >>= 1) s += __shfl_xor_sync(0xffffffffu, s, d);
    if (lane == 0) out[gph * N_OUTC + o] = s + lb[o];
}

// ---------------- launch -----------------------------------------------------
extern "C" void kernel_launch(void* const* d_in, const int* in_sizes, int n_in,
                              void* d_out, int out_size) {
    const float* x   = (const float*)d_in[0];
    const int*   ei  = (const int*)  d_in[1];
    const float* ew  = (const float*)d_in[2];
    const int*   bat = (const int*)  d_in[3];
    const float* P[18];
    for (int i = 0; i < 18; i++) P[i] = (const float*)d_in[4 + i];
    float* out = (float*)d_out;

    float *ph1, *pxo, *pst;
    __half *pw, *phh, *phl;
    cudaGetSymbolAddress((void**)&ph1, g_h1);
    cudaGetSymbolAddress((void**)&pxo, g_xo);
    cudaGetSymbolAddress((void**)&pst, g_stats);
    cudaGetSymbolAddress((void**)&pw,  g_w);
    cudaGetSymbolAddress((void**)&phh, g_hh);
    cudaGetSymbolAddress((void**)&phl, g_hl);

    cudaFuncSetAttribute(gemm1_kernel,
                         cudaFuncAttributeMaxDynamicSharedMemorySize, SMEM_G1);
    cudaFuncSetAttribute(gemm2_kernel<false>,
                         cudaFuncAttributeMaxDynamicSharedMemorySize, SMEM_G2);
    cudaFuncSetAttribute(gemm2_kernel<true>,
                         cudaFuncAttributeMaxDynamicSharedMemorySize, SMEM_G2);

    const int AGG_BLK = (N_NODESC + 7) / 8;

    setup_kernel<<<256, 256>>>(P[2], P[6], P[10], P[14]);
    bucket_build_kernel<<<(N_EDGESC + 255) / 256, 256>>>(ei, ew);

    const float* xin = x;
    for (int l = 0; l < 2; l++) {
        const float* We = P[l * 8 + 0];
        const float* be = P[l * 8 + 1];
        const float* b1 = P[l * 8 + 3];
        const float* gg = P[l * 8 + 4];
        const float* bt = P[l * 8 + 5];
        const float* b2 = P[l * 8 + 7];
        const __half* W1 = pw + (size_t)(l * 2 + 0) * CCH * CCH;
        const __half* W2 = pw + (size_t)(l * 2 + 1) * CCH * CCH;
        float* slot = pst + (size_t)l * 2 * CCH;

        node_agg_kernel<<<AGG_BLK, 256>>>(xin, We, be, phh, phl);
        gemm1_kernel<<<GRID_P, 256, SMEM_G1>>>(phh, phl, W1, b1, slot, ph1);
        if (l == 0) {
            gemm2_kernel<false><<<GRID_P, 256, SMEM_G2>>>(
                ph1, W2, b2, slot, gg, bt, pxo, bat);
        } else {
            gemm2_kernel<true><<<GRID_P, 256, SMEM_G2>>>(
                ph1, W2, b2, slot, gg, bt, pxo, bat);
        }
        xin = pxo;
    }

    final_linear_kernel<<<N_GRAPHS, 160>>>(P[16], P[17], out);
}